// round 7
// baseline (speedup 1.0000x reference)
#include <cuda_runtime.h>
#include <cuda.h>
#include <cuda_fp16.h>
#include <cstdint>

// ============================================================================
// TernaryLinear: out[m,n] = sum_k x[m,k] * sign(w[n,k])
//   M = 8192, N = 16384, K = 4096, fp32 in/out.
//
// fp16 single-plane GEMM on legacy mma.sync (tcgen05 unavailable: harness
// emits plain compute_103 PTX). A = fp16(x), B = sign(w) exact in fp16,
// fp32 accumulation. rel_err ~2.1e-4 (verified rounds 4-6).
//
// Round-7 change vs round 6 (2.08 ms, tensor=90.9%):
//   * PERSISTENT CTAs (grid=148, 1/SM) with a continuous cross-tile
//     pipeline: FULL/EMPTY ring indexed by a global iter counter, producer
//     refill target g+3 spills into the next tile, so fill latency and
//     epilogue overlap with TMA of the next tile. CTA launches 4096 -> 148.
//   * EMPTY arrive moved to just after the stage's last ldmatrix.
// ============================================================================

#define M_TOTAL 8192
#define K_TOTAL 4096
#define N_TOTAL 16384

// ------------------------- device scratch (no mallocs) ---------------------
__device__ __align__(1024) __half g_A[(size_t)M_TOTAL * K_TOTAL];   // 64 MB
__device__ __align__(1024) __half g_B[(size_t)N_TOTAL * K_TOTAL];   // 128 MB

// ------------------------------ PTX helpers --------------------------------
__device__ __forceinline__ uint32_t smem_u32(const void* p) {
    uint32_t a;
    asm("{ .reg .u64 t; cvta.to.shared.u64 t, %1; cvt.u32.u64 %0, t; }"
        : "=r"(a) : "l"(p));
    return a;
}

#define MBAR_INIT(addr, cnt) \
    asm volatile("mbarrier.init.shared.b64 [%0], %1;" :: "r"(addr), "r"(cnt) : "memory")

#define MBAR_EXPECT_TX(addr, bytes) \
    asm volatile("mbarrier.arrive.expect_tx.shared.b64 _, [%0], %1;" \
                 :: "r"(addr), "r"(bytes) : "memory")

#define MBAR_ARRIVE(addr) \
    asm volatile("mbarrier.arrive.shared.b64 _, [%0];" :: "r"(addr) : "memory")

#define MBAR_WAIT(addr, ph) do {                                              \
    asm volatile("{\n\t.reg .pred P1;\n\t"                                    \
        "WAIT_%=:\n\t"                                                        \
        "mbarrier.try_wait.parity.acquire.cta.shared::cta.b64 P1, [%0], %1, 0x989680;\n\t" \
        "@P1 bra.uni DONE_%=;\n\t"                                            \
        "bra.uni WAIT_%=;\n\t"                                                \
        "DONE_%=:\n\t}"                                                       \
        :: "r"(addr), "r"(ph) : "memory");                                    \
} while (0)

// relaxed: post-wait accesses are async-proxy (TMA) only
#define MBAR_WAIT_RELAXED(addr, ph) do {                                      \
    asm volatile("{\n\t.reg .pred P1;\n\t"                                    \
        "WAIT_%=:\n\t"                                                        \
        "mbarrier.try_wait.parity.relaxed.cta.shared::cta.b64 P1, [%0], %1, 0x989680;\n\t" \
        "@P1 bra.uni DONE_%=;\n\t"                                            \
        "bra.uni WAIT_%=;\n\t"                                                \
        "DONE_%=:\n\t}"                                                       \
        :: "r"(addr), "r"(ph) : "memory");                                    \
} while (0)

#define TMA_LOAD_2D(dst, map, cx, cy, mbar) \
    asm volatile("cp.async.bulk.tensor.2d.shared::cta.global.tile.mbarrier::complete_tx::bytes " \
                 "[%0], [%1, {%2, %3}], [%4];" \
                 :: "r"(dst), "l"(map), "r"(cx), "r"(cy), "r"(mbar) : "memory")

#define FENCE_PROXY_ASYNC() \
    asm volatile("fence.proxy.async.shared::cta;" ::: "memory")

#define LDSM4(r0, r1, r2, r3, addr)                                           \
    asm volatile("ldmatrix.sync.aligned.m8n8.x4.shared.b16 {%0,%1,%2,%3}, [%4];" \
        : "=r"(r0), "=r"(r1), "=r"(r2), "=r"(r3) : "r"(addr))

#define MMA_F16(d, a, b0, b1)                                                 \
    asm volatile("mma.sync.aligned.m16n8k16.row.col.f32.f16.f16.f32 "         \
        "{%0,%1,%2,%3}, {%4,%5,%6,%7}, {%8,%9}, {%0,%1,%2,%3};"               \
        : "+f"((d)[0]), "+f"((d)[1]), "+f"((d)[2]), "+f"((d)[3])              \
        : "r"((a)[0]), "r"((a)[1]), "r"((a)[2]), "r"((a)[3]),                 \
          "r"(b0), "r"(b1))

// -------------------- fused prologue: x->fp16, sign(w)->fp16 ---------------
__global__ void prep_kernel(const float4* __restrict__ x,
                            const float4* __restrict__ w,
                            int n4x, int n4w) {
    int i = blockIdx.x * blockDim.x + threadIdx.x;
    if (i < n4x) {
        float4 v = x[i];
        __half2* dst = reinterpret_cast<__half2*>(g_A) + (size_t)i * 2;
        dst[0] = __floats2half2_rn(v.x, v.y);
        dst[1] = __floats2half2_rn(v.z, v.w);
    } else {
        int j = i - n4x;
        if (j < n4w) {
            float4 v = w[j];
            float sx = (float)((v.x > 0.0f) - (v.x < 0.0f));
            float sy = (float)((v.y > 0.0f) - (v.y < 0.0f));
            float sz = (float)((v.z > 0.0f) - (v.z < 0.0f));
            float sw = (float)((v.w > 0.0f) - (v.w < 0.0f));
            __half2* dst = reinterpret_cast<__half2*>(g_B) + (size_t)j * 2;
            dst[0] = __floats2half2_rn(sx, sy);
            dst[1] = __floats2half2_rn(sz, sw);
        }
    }
}

// ------------------------------- GEMM kernel -------------------------------
// Persistent: grid = 148, each CTA grid-strides over 256x128 tiles.
// K-step 64 halves (128 B). 4-stage TMA ring (48 KB/stage), FULL (tx) +
// EMPTY (8 warp arrivals) barriers, global iteration counter across tiles.
// 256 threads = 8 warps (4x2); warp tile 64x64, 128 f32 accs / thread.

static constexpr int STAGES      = 4;
static constexpr int A_STG       = 32768;           // 256 rows x 128 B
static constexpr int B_STG       = 16384;           // 128 rows x 128 B
static constexpr int STAGE_BYTES = A_STG + B_STG;   // 48 KB
static constexpr int KITERS      = K_TOTAL / 64;    // 64
static constexpr int SMEM_DYN    = 1024 + 1024 + STAGES * STAGE_BYTES;
static constexpr int NSM         = 148;
static constexpr int TILES_TOTAL = (M_TOTAL / 256) * (N_TOTAL / 128);  // 4096

// linear tile id -> (gm, gn) with GROUP_M=8 swizzle (same map since round 2)
__device__ __forceinline__ void tile_coords(int t, int& gm, int& gn) {
    constexpr int TILES_N = N_TOTAL / 128;   // 128
    constexpr int GROUP_M = 8;
    const int per_group = GROUP_M * TILES_N; // 1024
    const int grp = t / per_group;
    const int ing = t % per_group;
    gm = (grp * GROUP_M + (ing % GROUP_M)) * 256;
    gn = (ing / GROUP_M) * 128;
}

__global__ void __launch_bounds__(256, 1) ternary_gemm_kernel(
    const __grid_constant__ CUtensorMap tma_a,
    const __grid_constant__ CUtensorMap tma_b,
    float* __restrict__ out)
{
    extern __shared__ uint8_t smem_raw[];
    const uint32_t sb    = smem_u32(smem_raw);
    const uint32_t base  = (sb + 1023u) & ~1023u;
    const uint32_t FULLB = base;          // 4 x 8B
    const uint32_t EMPTB = base + 64;     // 4 x 8B
    const uint32_t TILES = base + 1024;

    const int tid  = threadIdx.x;
    const int wid  = tid >> 5;
    const int lane = tid & 31;
    const int wm   = wid >> 1;            // 0..3  (M)
    const int wn   = wid & 1;             // 0..1  (N)
    const int bid  = blockIdx.x;

    const int ntiles = (TILES_TOTAL - bid + NSM - 1) / NSM;   // my tile count
    const int total_iters = ntiles * KITERS;                  // global g range

    // ---- init barriers ----
    if (tid == 0) {
        #pragma unroll
        for (int s = 0; s < STAGES; s++) {
            MBAR_INIT(FULLB + 8 * s, 1);
            MBAR_INIT(EMPTB + 8 * s, 8);
        }
        FENCE_PROXY_ASYNC();
    }
    __syncthreads();   // only CTA-wide barrier in the kernel

    // ---- producer prologue: fill global iters f = 0,1,2 ----
    if (tid == 0) {
        #pragma unroll
        for (int f = 0; f < STAGES - 1; f++) {
            if (f < total_iters) {
                int gm_, gn_;
                tile_coords(bid + (f >> 6) * NSM, gm_, gn_);
                MBAR_EXPECT_TX(FULLB + 8 * f, (uint32_t)STAGE_BYTES);
                const uint32_t tb = TILES + f * STAGE_BYTES;
                TMA_LOAD_2D(tb,         &tma_a, (f & 63) * 64, gm_, FULLB + 8 * f);
                TMA_LOAD_2D(tb + A_STG, &tma_b, (f & 63) * 64, gn_, FULLB + 8 * f);
            }
        }
    }

    // ---- per-lane ldmatrix address pieces (SW128 layout, verified R2-R6) ---
    const int mi  = lane >> 3;
    const int r   = lane & 7;
    const int hi2 = mi >> 1;
    const uint32_t a_row_off = (uint32_t)(wm * 64 + (mi & 1) * 8 + r) * 128;
    const uint32_t b_row_off = (uint32_t)(wn * 64 + hi2 * 8 + r) * 128;

    // ---- persistent tile loop ----
    for (int ti = 0; ti < ntiles; ti++) {
        int gm, gn;
        tile_coords(bid + ti * NSM, gm, gn);

        float acc[4][8][4];
        #pragma unroll
        for (int a = 0; a < 4; a++)
            #pragma unroll
            for (int b = 0; b < 8; b++)
                #pragma unroll
                for (int c = 0; c < 4; c++) acc[a][b][c] = 0.0f;

        for (int kt = 0; kt < KITERS; kt++) {
            const int g  = ti * KITERS + kt;        // global iteration
            const int s  = g & (STAGES - 1);
            const uint32_t full_ph = (uint32_t)((g >> 2) & 1);
            MBAR_WAIT(FULLB + 8 * s, full_ph);

            const uint32_t sa  = TILES + s * STAGE_BYTES;
            const uint32_t sbb = sa + A_STG;

            #pragma unroll
            for (int kc = 0; kc < 4; kc++) {   // 4 x k16 per 128B chunk
                const uint32_t ax = (uint32_t)((((kc << 1) | hi2) ^ r) << 4);
                const uint32_t bx = (uint32_t)((((kc << 1) | (mi & 1)) ^ r) << 4);

                uint32_t af[4][4], bf[8][2];
                #pragma unroll
                for (int mt = 0; mt < 4; mt++)
                    LDSM4(af[mt][0], af[mt][1], af[mt][2], af[mt][3],
                          sa + a_row_off + mt * 2048 + ax);
                #pragma unroll
                for (int j = 0; j < 4; j++)
                    LDSM4(bf[2 * j][0], bf[2 * j][1], bf[2 * j + 1][0], bf[2 * j + 1][1],
                          sbb + b_row_off + j * 2048 + bx);

                // stage data fully in registers after the last ldmatrix:
                // signal EMPTY before the final MMA block for producer lead
                if (kc == 3 && lane == 0) MBAR_ARRIVE(EMPTB + 8 * s);

                #pragma unroll
                for (int mt = 0; mt < 4; mt++)
                    #pragma unroll
                    for (int nt = 0; nt < 8; nt++)
                        MMA_F16(acc[mt][nt], af[mt], bf[nt][0], bf[nt][1]);
            }

            // refill global iter g+3 (may belong to the NEXT tile)
            if (tid == 0) {
                const int f = g + STAGES - 1;
                if (f < total_iters) {
                    const int ns = f & (STAGES - 1);
                    const int n  = f >> 2;               // fill instance
                    if (n >= 1)
                        MBAR_WAIT_RELAXED(EMPTB + 8 * ns, (uint32_t)((n - 1) & 1));
                    MBAR_EXPECT_TX(FULLB + 8 * ns, (uint32_t)STAGE_BYTES);
                    int gm_, gn_;
                    tile_coords(bid + (f >> 6) * NSM, gm_, gn_);
                    const uint32_t tb = TILES + ns * STAGE_BYTES;
                    TMA_LOAD_2D(tb,         &tma_a, (f & 63) * 64, gm_, FULLB + 8 * ns);
                    TMA_LOAD_2D(tb + A_STG, &tma_b, (f & 63) * 64, gn_, FULLB + 8 * ns);
                }
            }
        }

        // ---- epilogue for this tile (next tile's TMA already in flight) ----
        const int rbase = gm + wm * 64 + (lane >> 2);
        const int cbase = gn + wn * 64 + (lane & 3) * 2;
        #pragma unroll
        for (int mt = 0; mt < 4; mt++) {
            const int r0 = rbase + mt * 16;
            #pragma unroll
            for (int nt = 0; nt < 8; nt++) {
                const int c = cbase + nt * 8;
                float2 v;
                v.x = acc[mt][nt][0];
                v.y = acc[mt][nt][1];
                *reinterpret_cast<float2*>(out + (size_t)r0 * N_TOTAL + c) = v;
                v.x = acc[mt][nt][2];
                v.y = acc[mt][nt][3];
                *reinterpret_cast<float2*>(out + (size_t)(r0 + 8) * N_TOTAL + c) = v;
            }
        }
    }
}

// ------------------------------- host side ---------------------------------
typedef CUresult (*encode_fn_t)(CUtensorMap*, CUtensorMapDataType, cuuint32_t,
                                void*, const cuuint64_t*, const cuuint64_t*,
                                const cuuint32_t*, const cuuint32_t*,
                                CUtensorMapInterleave, CUtensorMapSwizzle,
                                CUtensorMapL2promotion, CUtensorMapFloatOOBfill);

static void make_map_f16(CUtensorMap* m, void* ptr,
                         uint64_t inner, uint64_t outer,
                         uint32_t box_i, uint32_t box_o) {
    encode_fn_t fn = nullptr;
    cudaDriverEntryPointQueryResult st;
    cudaGetDriverEntryPointByVersion("cuTensorMapEncodeTiled", (void**)&fn,
                                     12000, cudaEnableDefault, &st);
    if (!fn) return;
    cuuint64_t dims[2]    = {inner, outer};
    cuuint64_t strides[1] = {inner * 2};      // bytes (fp16)
    cuuint32_t box[2]     = {box_i, box_o};
    cuuint32_t es[2]      = {1, 1};
    fn(m, CU_TENSOR_MAP_DATA_TYPE_UINT16, 2, ptr, dims, strides, box, es,
       CU_TENSOR_MAP_INTERLEAVE_NONE, CU_TENSOR_MAP_SWIZZLE_128B,
       CU_TENSOR_MAP_L2_PROMOTION_L2_128B, CU_TENSOR_MAP_FLOAT_OOB_FILL_NONE);
}

extern "C" void kernel_launch(void* const* d_in, const int* in_sizes, int n_in,
                              void* d_out, int out_size) {
    const float* x = (const float*)d_in[0];   // [2,4096,4096]
    const float* w = (const float*)d_in[1];   // [16384,4096]
    float* out = (float*)d_out;               // [2,4096,16384]

    // fused prologue (1 launch so ncu -s5 -c1 lands on the GEMM)
    {
        const int n4x = (M_TOTAL * K_TOTAL) / 4;
        const int n4w = (N_TOTAL * K_TOTAL) / 4;
        const int total = n4x + n4w;
        prep_kernel<<<(total + 255) / 256, 256>>>((const float4*)x,
                                                  (const float4*)w, n4x, n4w);
    }

    void *p_a = nullptr, *p_b = nullptr;
    cudaGetSymbolAddress(&p_a, g_A);
    cudaGetSymbolAddress(&p_b, g_B);

    CUtensorMap mA, mB;
    make_map_f16(&mA, p_a, K_TOTAL, M_TOTAL, 64, 256);
    make_map_f16(&mB, p_b, K_TOTAL, N_TOTAL, 64, 128);

    cudaFuncSetAttribute(ternary_gemm_kernel,
                         cudaFuncAttributeMaxDynamicSharedMemorySize, SMEM_DYN);

    ternary_gemm_kernel<<<NSM, 256, SMEM_DYN>>>(mA, mB, out);
}